// round 1
// baseline (speedup 1.0000x reference)
#include <cuda_runtime.h>

// FullAttention: out[b,l,h,d] = softmax_s( scale * (Q·K^T + mask) ) · V
// B=2, L=S=2048, H=16, E=D=64, scale = 1/sqrt(64) = 0.125
// Flash-attention, one CTA per (64 L-rows, h, b), online softmax,
// mma.sync m16n8k8 TF32 for both QK^T and P·V.

namespace {
constexpr int Bb = 2, Ll = 2048, Ss = 2048, Hh = 16, Ee = 64, Dd = 64;
constexpr int BM = 64;   // L rows per CTA
constexpr int BN = 64;   // S tile
constexpr float SCALE = 0.125f;

__device__ __forceinline__ unsigned f2tf(float x) {
    unsigned u;
    asm("cvt.rna.tf32.f32 %0, %1;" : "=r"(u) : "f"(x));
    return u;
}

__device__ __forceinline__ void mma8(float* c, const unsigned* a, unsigned b0, unsigned b1) {
    asm volatile(
        "mma.sync.aligned.m16n8k8.row.col.f32.tf32.tf32.f32 "
        "{%0,%1,%2,%3},{%4,%5,%6,%7},{%8,%9},{%0,%1,%2,%3};\n"
        : "+f"(c[0]), "+f"(c[1]), "+f"(c[2]), "+f"(c[3])
        : "r"(a[0]), "r"(a[1]), "r"(a[2]), "r"(a[3]), "r"(b0), "r"(b1));
}
}  // namespace

__global__ void __launch_bounds__(128, 2) fa_tf32_kernel(
    const float* __restrict__ Q, const float* __restrict__ K,
    const float* __restrict__ V, const float* __restrict__ M,
    float* __restrict__ O)
{
    // sK stride 68: fragment reads (row=g 0..7, col=t 0..3) hit banks (4g+t)%32 — all distinct.
    // sV stride 72: fragment reads (row=t 0..3(+4), col=g 0..7) hit banks (8t+g)%32 — all distinct.
    __shared__ unsigned sK[BN][68];   // K tile (tf32); reused as P tile after QK mma
    __shared__ unsigned sV[BN][72];   // V tile (tf32)

    const int l0   = blockIdx.x * BM;
    const int h    = blockIdx.y;
    const int b    = blockIdx.z;
    const int tid  = threadIdx.x;
    const int warp = tid >> 5;
    const int lane = tid & 31;
    const int g    = lane >> 2;   // groupID (row within 8)
    const int t    = lane & 3;    // threadID_in_group

    const int row0 = l0 + warp * 16 + g;
    const int row1 = row0 + 8;

    // ---- Q A-fragments in registers: 8 k-tiles of m16n8k8 ----
    unsigned aQ[8][4];
    {
        const float* qb = Q + ((b * Ll + l0 + warp * 16) * Hh + h) * Ee;
        const int rs = Hh * Ee;  // row stride in floats
        #pragma unroll
        for (int kt = 0; kt < 8; kt++) {
            int c = kt * 8 + t;
            aQ[kt][0] = f2tf(__ldg(qb + g * rs + c));
            aQ[kt][1] = f2tf(__ldg(qb + (g + 8) * rs + c));
            aQ[kt][2] = f2tf(__ldg(qb + g * rs + c + 4));
            aQ[kt][3] = f2tf(__ldg(qb + (g + 8) * rs + c + 4));
        }
    }

    // ---- Output accumulators + online softmax state ----
    float acc[8][4];
    #pragma unroll
    for (int nt = 0; nt < 8; nt++) {
        acc[nt][0] = 0.f; acc[nt][1] = 0.f; acc[nt][2] = 0.f; acc[nt][3] = 0.f;
    }
    float mrow0 = -1e30f, mrow1 = -1e30f;
    float lrow0 = 0.f, lrow1 = 0.f;

    for (int s0 = 0; s0 < Ss; s0 += BN) {
        __syncthreads();  // previous iteration's P/V smem reads complete

        // ---- Cooperative load of K and V tiles (coalesced float4, cvt to tf32) ----
        #pragma unroll
        for (int i = tid; i < (BN * Ee) / 4; i += 128) {
            int r = i >> 4;
            int c = (i & 15) << 2;
            int gidx = ((b * Ss + s0 + r) * Hh + h) * Ee + c;  // same offset for K and V (E==D)
            float4 kv = __ldg((const float4*)(K + gidx));
            sK[r][c + 0] = f2tf(kv.x); sK[r][c + 1] = f2tf(kv.y);
            sK[r][c + 2] = f2tf(kv.z); sK[r][c + 3] = f2tf(kv.w);
            float4 vv = __ldg((const float4*)(V + gidx));
            sV[r][c + 0] = f2tf(vv.x); sV[r][c + 1] = f2tf(vv.y);
            sV[r][c + 2] = f2tf(vv.z); sV[r][c + 3] = f2tf(vv.w);
        }
        __syncthreads();

        // ---- Scores: S = Q · K^T  (16x64 per warp) ----
        float sc[8][4];
        #pragma unroll
        for (int nt = 0; nt < 8; nt++) {
            sc[nt][0] = 0.f; sc[nt][1] = 0.f; sc[nt][2] = 0.f; sc[nt][3] = 0.f;
        }
        #pragma unroll
        for (int kt = 0; kt < 8; kt++) {
            #pragma unroll
            for (int nt = 0; nt < 8; nt++) {
                // B fragment (k=e, n=s): b0=(t, g), b1=(t+4, g) -> K[s=nt*8+g][e=kt*8+t(+4)]
                unsigned b0 = sK[nt * 8 + g][kt * 8 + t];
                unsigned b1 = sK[nt * 8 + g][kt * 8 + t + 4];
                mma8(sc[nt], aQ[kt], b0, b1);
            }
        }

        // ---- logits = scale * (score + mask); row max ----
        float rmax0 = -1e30f, rmax1 = -1e30f;
        #pragma unroll
        for (int nt = 0; nt < 8; nt++) {
            int scol = s0 + nt * 8 + 2 * t;
            float2 m0v = __ldg((const float2*)(M + row0 * Ss + scol));
            float2 m1v = __ldg((const float2*)(M + row1 * Ss + scol));
            sc[nt][0] = SCALE * (sc[nt][0] + m0v.x);
            sc[nt][1] = SCALE * (sc[nt][1] + m0v.y);
            sc[nt][2] = SCALE * (sc[nt][2] + m1v.x);
            sc[nt][3] = SCALE * (sc[nt][3] + m1v.y);
            rmax0 = fmaxf(rmax0, fmaxf(sc[nt][0], sc[nt][1]));
            rmax1 = fmaxf(rmax1, fmaxf(sc[nt][2], sc[nt][3]));
        }
        rmax0 = fmaxf(rmax0, __shfl_xor_sync(0xffffffffu, rmax0, 1));
        rmax0 = fmaxf(rmax0, __shfl_xor_sync(0xffffffffu, rmax0, 2));
        rmax1 = fmaxf(rmax1, __shfl_xor_sync(0xffffffffu, rmax1, 1));
        rmax1 = fmaxf(rmax1, __shfl_xor_sync(0xffffffffu, rmax1, 2));

        float mn0 = fmaxf(mrow0, rmax0);
        float mn1 = fmaxf(mrow1, rmax1);
        float al0 = __expf(mrow0 - mn0);
        float al1 = __expf(mrow1 - mn1);
        mrow0 = mn0; mrow1 = mn1;

        float rs0 = 0.f, rs1 = 0.f;
        #pragma unroll
        for (int nt = 0; nt < 8; nt++) {
            sc[nt][0] = __expf(sc[nt][0] - mn0); rs0 += sc[nt][0];
            sc[nt][1] = __expf(sc[nt][1] - mn0); rs0 += sc[nt][1];
            sc[nt][2] = __expf(sc[nt][2] - mn1); rs1 += sc[nt][2];
            sc[nt][3] = __expf(sc[nt][3] - mn1); rs1 += sc[nt][3];
        }
        rs0 += __shfl_xor_sync(0xffffffffu, rs0, 1);
        rs0 += __shfl_xor_sync(0xffffffffu, rs0, 2);
        rs1 += __shfl_xor_sync(0xffffffffu, rs1, 1);
        rs1 += __shfl_xor_sync(0xffffffffu, rs1, 2);
        lrow0 = lrow0 * al0 + rs0;
        lrow1 = lrow1 * al1 + rs1;

        // ---- rescale O accumulators ----
        #pragma unroll
        for (int nt = 0; nt < 8; nt++) {
            acc[nt][0] *= al0; acc[nt][1] *= al0;
            acc[nt][2] *= al1; acc[nt][3] *= al1;
        }

        __syncthreads();  // all warps finished reading sK (K tile) before P overwrite

        // ---- Store P (tf32) into sK, own 16 rows (C-layout -> memory) ----
        #pragma unroll
        for (int nt = 0; nt < 8; nt++) {
            sK[warp * 16 + g][nt * 8 + 2 * t]         = f2tf(sc[nt][0]);
            sK[warp * 16 + g][nt * 8 + 2 * t + 1]     = f2tf(sc[nt][1]);
            sK[warp * 16 + g + 8][nt * 8 + 2 * t]     = f2tf(sc[nt][2]);
            sK[warp * 16 + g + 8][nt * 8 + 2 * t + 1] = f2tf(sc[nt][3]);
        }
        __syncwarp();  // each warp reads only its own P rows

        // ---- O += P · V ----
        #pragma unroll
        for (int kt = 0; kt < 8; kt++) {
            unsigned aP[4] = {
                sK[warp * 16 + g][kt * 8 + t],
                sK[warp * 16 + g + 8][kt * 8 + t],
                sK[warp * 16 + g][kt * 8 + t + 4],
                sK[warp * 16 + g + 8][kt * 8 + t + 4]
            };
            #pragma unroll
            for (int nt = 0; nt < 8; nt++) {
                // B fragment (k=s, n=d): b0 = V[s=kt*8+t][d=nt*8+g]
                unsigned b0 = sV[kt * 8 + t][nt * 8 + g];
                unsigned b1 = sV[kt * 8 + t + 4][nt * 8 + g];
                mma8(acc[nt], aP, b0, b1);
            }
        }
    }

    // ---- Epilogue: normalize and write out[b, l, h, d] ----
    float inv0 = 1.f / lrow0;
    float inv1 = 1.f / lrow1;
    #pragma unroll
    for (int nt = 0; nt < 8; nt++) {
        int c = nt * 8 + 2 * t;
        float2 o0 = make_float2(acc[nt][0] * inv0, acc[nt][1] * inv0);
        float2 o1 = make_float2(acc[nt][2] * inv1, acc[nt][3] * inv1);
        *(float2*)(O + ((b * Ll + row0) * Hh + h) * Dd + c) = o0;
        *(float2*)(O + ((b * Ll + row1) * Hh + h) * Dd + c) = o1;
    }
}

extern "C" void kernel_launch(void* const* d_in, const int* in_sizes, int n_in,
                              void* d_out, int out_size) {
    const float* Q = (const float*)d_in[0];  // [B, L, H, E]
    const float* K = (const float*)d_in[1];  // [B, S, H, E]
    const float* V = (const float*)d_in[2];  // [B, S, H, D]
    const float* M = (const float*)d_in[3];  // [1, 1, L, S]
    float* O = (float*)d_out;                // [B, L, H, D]

    dim3 grid(Ll / BM, Hh, Bb);
    dim3 block(128);
    fa_tf32_kernel<<<grid, block>>>(Q, K, V, M, O);
}